// round 8
// baseline (speedup 1.0000x reference)
#include <cuda_runtime.h>
#include <math.h>
#include <stdint.h>

#define NN   512
#define DD   32

// ---------------- device scratch ----------------
__device__ float g_h[NN * DD];
__device__ float g_u[NN * 64];
__device__ float g_v[NN * 64];
__device__ float g_msum[NN * DD];
__device__ float g_Jt[NN * NN];

// ---------------- helpers ----------------
static __device__ __forceinline__ uint32_t cvt2(float lo, float hi) {
    uint32_t r;
    asm("cvt.rn.bf16x2.f32 %0, %1, %2;" : "=r"(r) : "f"(hi), "f"(lo));
    return r;
}
static __device__ __forceinline__ void mma16816(float* d, const uint32_t* a,
                                                uint32_t b0, uint32_t b1) {
    asm volatile(
        "mma.sync.aligned.m16n8k16.row.col.f32.bf16.bf16.f32 "
        "{%0,%1,%2,%3}, {%4,%5,%6,%7}, {%8,%9}, {%0,%1,%2,%3};"
        : "+f"(d[0]), "+f"(d[1]), "+f"(d[2]), "+f"(d[3])
        : "r"(a[0]), "r"(a[1]), "r"(a[2]), "r"(a[3]), "r"(b0), "r"(b1));
}

// ---------------- init ----------------
__global__ void k_init() {
    int t = blockIdx.x * blockDim.x + threadIdx.x;
    if (t < NN * DD) g_h[t] = 0.f;
}

// ---------------- transpose J ----------------
__global__ void k_tr(const float* __restrict__ J) {
    __shared__ float tile[32][33];
    int bx = blockIdx.x * 32, by = blockIdx.y * 32;
    int tx = threadIdx.x, ty = threadIdx.y;
    for (int yy = ty; yy < 32; yy += 8)
        tile[yy][tx] = J[(by + yy) * NN + bx + tx];
    __syncthreads();
    for (int yy = ty; yy < 32; yy += 8)
        g_Jt[(size_t)(bx + yy) * NN + by + tx] = tile[tx][yy];
}

// ---------------- u/v precompute ----------------
__global__ void __launch_bounds__(256) k_uv(const float* __restrict__ b,
                                            const float* __restrict__ W1,  // (64,67)
                                            const float* __restrict__ b1) {
    __shared__ float W1s[64][69];
    __shared__ float hs[8][32];
    __shared__ float bv[8];
    int t = threadIdx.x;
    int n0 = blockIdx.x * 8;
    for (int idx = t; idx < 64 * 67; idx += 256)
        W1s[idx / 67][idx % 67] = W1[idx];
    {
        int nl = t >> 5, c = t & 31;
        hs[nl][c] = g_h[(n0 + nl) * DD + c];
    }
    if (t < 8) bv[t] = b[n0 + t];
    __syncthreads();
    int k = t & 63;
    int nlb = t >> 6;
    float b1k = b1[k];
#pragma unroll
    for (int rep = 0; rep < 2; rep++) {
        int nl = nlb + rep * 4;
        float uu = bv[nl] * W1s[k][65];
        float vv = bv[nl] * W1s[k][66] + b1k;
#pragma unroll
        for (int d = 0; d < DD; d++) {
            uu = fmaf(hs[nl][d], W1s[k][d], uu);
            vv = fmaf(hs[nl][d], W1s[k][DD + d], vv);
        }
        g_u[(n0 + nl) * 64 + k] = uu;
        g_v[(n0 + nl) * 64 + k] = vv;
    }
}

// ---------------- edge MLP + message sum: all-register, sync-free hot loop ----
// 512 blocks (one per j), 128 threads = 4 warps. Each warp processes eight
// m16 i-tiles. m1 fragments are built in registers from g_u/g_Jt loads;
// MMA1 D-fragments are converted in registers into MMA2 A-fragments
// (layout identity), so there is NO smem round-trip and NO sync in the loop.
__global__ void __launch_bounds__(128, 4)
k_msg(const float* __restrict__ W1,
      const float* __restrict__ W2,   // (64,64)
      const float* __restrict__ b2,
      const float* __restrict__ W3,   // (32,64)
      const float* __restrict__ b3) {
    __shared__ uint32_t W2s[64][36];   // bf16x2 words, padded rows (conflict-free)
    __shared__ uint32_t W3s[32][36];
    __shared__ float v_s[64], wj_s[64], b2_s[64], b3_s[32];
    __shared__ float wpart[4][32];

    int t = threadIdx.x;
    int lane = t & 31, wid = t >> 5;
    int j = blockIdx.x;

    for (int idx = t; idx < 2048; idx += 128) {
        int r = idx >> 5, w = idx & 31;
        float2 p = *(const float2*)(W2 + r * 64 + 2 * w);
        W2s[r][w] = cvt2(p.x, p.y);
    }
    for (int idx = t; idx < 1024; idx += 128) {
        int r = idx >> 5, w = idx & 31;
        float2 p = *(const float2*)(W3 + r * 64 + 2 * w);
        W3s[r][w] = cvt2(p.x, p.y);
    }
    if (t < 64) {
        v_s[t]  = g_v[j * 64 + t];
        wj_s[t] = W1[t * 67 + 64];
        b2_s[t] = b2[t];
    }
    if (t < 32) b3_s[t] = b3[t];
    __syncthreads();

    const int q2 = (lane & 3) * 2;
    const int rsub = lane >> 2;
    const int brow = lane >> 2;        // B-fragment row selector
    const int bcol = lane & 3;

    float acc[4][2];
#pragma unroll
    for (int nt = 0; nt < 4; nt++) acc[nt][0] = acc[nt][1] = 0.f;

#pragma unroll 1
    for (int tb = wid; tb < 32; tb += 4) {
        int r0 = tb * 16 + rsub;                  // global i row
        float J0 = g_Jt[(size_t)j * NN + r0];
        float J1 = g_Jt[(size_t)j * NN + r0 + 8];

        // ---- build m1 A-fragments in registers ----
        uint32_t a1[4][4];
#pragma unroll
        for (int kt = 0; kt < 4; kt++) {
            int k0 = kt * 16 + q2;
            float2 ua = *(const float2*)(g_u + r0 * 64 + k0);
            float2 ub = *(const float2*)(g_u + r0 * 64 + k0 + 8);
            float2 uc = *(const float2*)(g_u + (r0 + 8) * 64 + k0);
            float2 ud = *(const float2*)(g_u + (r0 + 8) * 64 + k0 + 8);
            float va0 = v_s[k0],     va1 = v_s[k0 + 1];
            float vb0 = v_s[k0 + 8], vb1 = v_s[k0 + 9];
            float wa0 = wj_s[k0],     wa1 = wj_s[k0 + 1];
            float wb0 = wj_s[k0 + 8], wb1 = wj_s[k0 + 9];
            a1[kt][0] = cvt2(fmaxf(fmaf(J0, wa0, ua.x + va0), 0.f),
                             fmaxf(fmaf(J0, wa1, ua.y + va1), 0.f));
            a1[kt][1] = cvt2(fmaxf(fmaf(J1, wa0, uc.x + va0), 0.f),
                             fmaxf(fmaf(J1, wa1, uc.y + va1), 0.f));
            a1[kt][2] = cvt2(fmaxf(fmaf(J0, wb0, ub.x + vb0), 0.f),
                             fmaxf(fmaf(J0, wb1, ub.y + vb1), 0.f));
            a1[kt][3] = cvt2(fmaxf(fmaf(J1, wb0, ud.x + vb0), 0.f),
                             fmaxf(fmaf(J1, wb1, ud.y + vb1), 0.f));
        }

        // ---- MMA1: d1 = m1 @ W2^T (16 x 64, K=64) ----
        float d1[8][4];
#pragma unroll
        for (int nt = 0; nt < 8; nt++) {
            d1[nt][0] = d1[nt][1] = d1[nt][2] = d1[nt][3] = 0.f;
#pragma unroll
            for (int kt = 0; kt < 4; kt++) {
                uint32_t b0 = W2s[nt * 8 + brow][kt * 8 + bcol];
                uint32_t b1 = W2s[nt * 8 + brow][kt * 8 + bcol + 4];
                mma16816(d1[nt], a1[kt], b0, b1);
            }
        }

        // ---- in-register convert: relu(d1 + b2) -> MMA2 A-fragments ----
        uint32_t a2f[4][4];
#pragma unroll
        for (int kt = 0; kt < 4; kt++) {
            int n0i = 2 * kt, n1i = 2 * kt + 1;
            float p00 = b2_s[n0i * 8 + q2],  p01 = b2_s[n0i * 8 + q2 + 1];
            float p10 = b2_s[n1i * 8 + q2],  p11 = b2_s[n1i * 8 + q2 + 1];
            a2f[kt][0] = cvt2(fmaxf(d1[n0i][0] + p00, 0.f),
                              fmaxf(d1[n0i][1] + p01, 0.f));
            a2f[kt][1] = cvt2(fmaxf(d1[n0i][2] + p00, 0.f),
                              fmaxf(d1[n0i][3] + p01, 0.f));
            a2f[kt][2] = cvt2(fmaxf(d1[n1i][0] + p10, 0.f),
                              fmaxf(d1[n1i][1] + p11, 0.f));
            a2f[kt][3] = cvt2(fmaxf(d1[n1i][2] + p10, 0.f),
                              fmaxf(d1[n1i][3] + p11, 0.f));
        }

        // ---- MMA2: d2 = m2 @ W3^T (16 x 32, K=64) + epi2 ----
#pragma unroll
        for (int nt = 0; nt < 4; nt++) {
            float d2[4] = {0.f, 0.f, 0.f, 0.f};
#pragma unroll
            for (int kt = 0; kt < 4; kt++) {
                uint32_t b0 = W3s[nt * 8 + brow][kt * 8 + bcol];
                uint32_t b1 = W3s[nt * 8 + brow][kt * 8 + bcol + 4];
                mma16816(d2, a2f[kt], b0, b1);
            }
            float bb0 = b3_s[nt * 8 + q2];
            float bb1 = b3_s[nt * 8 + q2 + 1];
            acc[nt][0] += fmaxf(d2[0] + bb0, 0.f) + fmaxf(d2[2] + bb0, 0.f);
            acc[nt][1] += fmaxf(d2[1] + bb1, 0.f) + fmaxf(d2[3] + bb1, 0.f);
        }
    }

    // ---- reduction: lanes sharing (lane&3) hold the same columns ----
#pragma unroll
    for (int nt = 0; nt < 4; nt++)
#pragma unroll
        for (int c = 0; c < 2; c++) {
            float v = acc[nt][c];
            v += __shfl_xor_sync(0xFFFFFFFFu, v, 4);
            v += __shfl_xor_sync(0xFFFFFFFFu, v, 8);
            v += __shfl_xor_sync(0xFFFFFFFFu, v, 16);
            acc[nt][c] = v;
        }
    if (lane < 4) {
#pragma unroll
        for (int nt = 0; nt < 4; nt++) {
            wpart[wid][nt * 8 + lane * 2]     = acc[nt][0];
            wpart[wid][nt * 8 + lane * 2 + 1] = acc[nt][1];
        }
    }
    __syncthreads();
    if (t < 32)
        g_msum[j * 32 + t] = wpart[0][t] + wpart[1][t] + wpart[2][t] + wpart[3][t];
}

// ---------------- GRU ----------------
__global__ void __launch_bounds__(384) k_gru(const float* __restrict__ Wih,  // (96,64)
                                             const float* __restrict__ Whh,  // (96,32)
                                             const float* __restrict__ bih,
                                             const float* __restrict__ bhh) {
    __shared__ float Wih_s[96][65];
    __shared__ float Whh_s[96][33];
    __shared__ float x_s[4][64];
    __shared__ float gi_s[4][96], gh_s[4][96];
    int t = threadIdx.x;
    int n0 = blockIdx.x * 4;
    for (int idx = t; idx < 96 * 64; idx += 384) Wih_s[idx >> 6][idx & 63] = Wih[idx];
    for (int idx = t; idx < 96 * 32; idx += 384) Whh_s[idx >> 5][idx & 31] = Whh[idx];
    if (t < 256) {
        int nl = t >> 6, c = t & 63;
        x_s[nl][c] = (c < 32) ? g_h[(n0 + nl) * DD + c]
                              : g_msum[(n0 + nl) * DD + (c - 32)];
    }
    __syncthreads();
    int nl = t / 96, q = t % 96;
    float gi = bih[q], gh = bhh[q];
#pragma unroll
    for (int c = 0; c < 64; c++) gi = fmaf(x_s[nl][c], Wih_s[q][c], gi);
#pragma unroll
    for (int c = 0; c < 32; c++) gh = fmaf(x_s[nl][c], Whh_s[q][c], gh);
    gi_s[nl][q] = gi; gh_s[nl][q] = gh;
    __syncthreads();
    if (q < 32) {
        float r  = 1.f / (1.f + expf(-(gi_s[nl][q]      + gh_s[nl][q])));
        float z  = 1.f / (1.f + expf(-(gi_s[nl][32 + q] + gh_s[nl][32 + q])));
        float ng = tanhf(gi_s[nl][64 + q] + r * gh_s[nl][64 + q]);
        g_h[(n0 + nl) * DD + q] = (1.f - z) * ng + z * x_s[nl][q];
    }
}

// ---------------- readout ----------------
__global__ void k_readout(const float* __restrict__ W1, const float* __restrict__ b1,
                          const float* __restrict__ W2, const float* __restrict__ b2,
                          const float* __restrict__ W3, const float* __restrict__ b3,
                          float* __restrict__ out) {
    int jn = blockIdx.x;
    int k = threadIdx.x;                 // 64 threads
    __shared__ float hs[DD], y1[64], y2[64];
    if (k < DD) hs[k] = g_h[jn * DD + k];
    __syncthreads();
    float a = b1[k];
    const float* w1 = W1 + k * DD;
#pragma unroll
    for (int c = 0; c < DD; c++) a = fmaf(hs[c], w1[c], a);
    y1[k] = fmaxf(a, 0.f);
    __syncthreads();
    float a2 = b2[k];
    const float* w2 = W2 + k * 64;
#pragma unroll
    for (int c = 0; c < 64; c++) a2 = fmaf(y1[c], w2[c], a2);
    y2[k] = fmaxf(a2, 0.f);
    __syncthreads();
    if (k < 2) {
        float a3 = b3[k];
        const float* w3 = W3 + k * 64;
#pragma unroll
        for (int c = 0; c < 64; c++) a3 = fmaf(y2[c], w3[c], a3);
        a3 = fmaxf(a3, 0.f);
        out[jn * 2 + k] = 1.f / (1.f + expf(-a3));
    }
}

extern "C" void kernel_launch(void* const* d_in, const int* in_sizes, int n_in,
                              void* d_out, int out_size) {
    const float* J   = (const float*)d_in[0];
    const float* b   = (const float*)d_in[1];
    const float* W1  = (const float*)d_in[2];
    const float* b1  = (const float*)d_in[3];
    const float* W2  = (const float*)d_in[4];
    const float* b2  = (const float*)d_in[5];
    const float* W3  = (const float*)d_in[6];
    const float* b3  = (const float*)d_in[7];
    const float* Wih = (const float*)d_in[8];
    const float* Whh = (const float*)d_in[9];
    const float* bih = (const float*)d_in[10];
    const float* bhh = (const float*)d_in[11];
    const float* rW1 = (const float*)d_in[12];
    const float* rb1 = (const float*)d_in[13];
    const float* rW2 = (const float*)d_in[14];
    const float* rb2 = (const float*)d_in[15];
    const float* rW3 = (const float*)d_in[16];
    const float* rb3 = (const float*)d_in[17];
    float* out = (float*)d_out;

    k_init<<<16, 1024>>>();
    k_tr<<<dim3(16, 16), dim3(32, 8)>>>(J);
    for (int s = 0; s < 5; s++) {
        k_uv<<<64, 256>>>(b, W1, b1);
        k_msg<<<NN, 128>>>(W1, W2, b2, W3, b3);
        k_gru<<<128, 384>>>(Wih, Whh, bih, bhh);
    }
    k_readout<<<NN, 64>>>(rW1, rb1, rW2, rb2, rW3, rb3, out);
}

// round 12
// speedup vs baseline: 1.0112x; 1.0112x over previous
#include <cuda_runtime.h>
#include <math.h>
#include <stdint.h>

#define NN   512
#define DD   32

// ---------------- device scratch ----------------
__device__ float    g_h[NN * DD];        // fp32 state (GRU math)
__device__ uint32_t g_hb[NN * 16];       // bf16x2-packed h rows (16 words/row)
__device__ float    g_v[NN * 64];
__device__ float    g_msum[NN * DD];
__device__ float    g_Jt[NN * NN];

// ---------------- helpers ----------------
static __device__ __forceinline__ uint32_t cvt2(float lo, float hi) {
    uint32_t r;
    asm("cvt.rn.bf16x2.f32 %0, %1, %2;" : "=r"(r) : "f"(hi), "f"(lo));
    return r;
}
static __device__ __forceinline__ void mma16816(float* d, const uint32_t* a,
                                                uint32_t b0, uint32_t b1) {
    asm volatile(
        "mma.sync.aligned.m16n8k16.row.col.f32.bf16.bf16.f32 "
        "{%0,%1,%2,%3}, {%4,%5,%6,%7}, {%8,%9}, {%0,%1,%2,%3};"
        : "+f"(d[0]), "+f"(d[1]), "+f"(d[2]), "+f"(d[3])
        : "r"(a[0]), "r"(a[1]), "r"(a[2]), "r"(a[3]), "r"(b0), "r"(b1));
}

// ---------------- init ----------------
__global__ void k_init() {
    int t = blockIdx.x * blockDim.x + threadIdx.x;
    if (t < NN * DD) g_h[t] = 0.f;
    if (t < NN * 16) g_hb[t] = 0u;
}

// ---------------- transpose J ----------------
__global__ void k_tr(const float* __restrict__ J) {
    __shared__ float tile[32][33];
    int bx = blockIdx.x * 32, by = blockIdx.y * 32;
    int tx = threadIdx.x, ty = threadIdx.y;
    for (int yy = ty; yy < 32; yy += 8)
        tile[yy][tx] = J[(by + yy) * NN + bx + tx];
    __syncthreads();
    for (int yy = ty; yy < 32; yy += 8)
        g_Jt[(size_t)(bx + yy) * NN + by + tx] = tile[tx][yy];
}

// ---------------- v precompute (h@Wj^T + b*wbj + b1) ----------------
__global__ void __launch_bounds__(256) k_v(const float* __restrict__ b,
                                           const float* __restrict__ W1,  // (64,67)
                                           const float* __restrict__ b1) {
    __shared__ float W1s[64][35];   // Wj part (cols 32..63) + wbj (col 66)
    __shared__ float hs[8][32];
    __shared__ float bv[8];
    int t = threadIdx.x;
    int n0 = blockIdx.x * 8;
    for (int idx = t; idx < 64 * 32; idx += 256)
        W1s[idx >> 5][idx & 31] = W1[(idx >> 5) * 67 + 32 + (idx & 31)];
    if (t < 64) W1s[t][32] = W1[t * 67 + 66];   // wbj
    {
        int nl = t >> 5, c = t & 31;
        hs[nl][c] = g_h[(n0 + nl) * DD + c];
    }
    if (t < 8) bv[t] = b[n0 + t];
    __syncthreads();
    int k = t & 63;
    int nlb = t >> 6;
    float b1k = b1[k];
#pragma unroll
    for (int rep = 0; rep < 2; rep++) {
        int nl = nlb + rep * 4;
        float vv = bv[nl] * W1s[k][32] + b1k;
#pragma unroll
        for (int d = 0; d < DD; d++)
            vv = fmaf(hs[nl][d], W1s[k][d], vv);
        g_v[(n0 + nl) * 64 + k] = vv;
    }
}

// ---------------- edge MLP + message sum: 3-stage register MMA chain ----------
// 512 blocks (one per j), 128 threads = 4 warps. Stage bf16 h (swizzled) +
// packed (b,J) in smem once; per m16 i-tile: MMA0 ([h|b|J]@W1i^T, K=48) ->
// +v relu -> MMA1 (@W2^T) -> +b2 relu -> MMA2 (@W3^T) -> +b3 relu colsum.
// All inter-stage handoff is the D-frag == A-frag register identity.
#define OFF_H   0            // 512*16 words, XOR-swizzled
#define OFF_W0  32768        // [64][28] words
#define OFF_W2  39936        // [64][36]
#define OFF_W3  49152        // [32][36]
#define OFF_BJ  53760        // 512 words (b,J) bf16x2
#define OFF_V   55808        // 64 f
#define OFF_B2  56064        // 64 f
#define OFF_B3  56320        // 32 f
#define OFF_WP  56448        // 4*32 f
#define MSG_SMEM 57344

__global__ void __launch_bounds__(128, 4)
k_msg(const float* __restrict__ b_in,
      const float* __restrict__ W1,   // (64,67): [Wi|Wj|wJ|wbi|wbj]
      const float* __restrict__ W2,   // (64,64)
      const float* __restrict__ b2,
      const float* __restrict__ W3,   // (32,64)
      const float* __restrict__ b3) {
    extern __shared__ char sm[];
    uint32_t* h_s  = (uint32_t*)(sm + OFF_H);
    uint32_t (*W0s)[28] = (uint32_t(*)[28])(sm + OFF_W0);
    uint32_t (*W2s)[36] = (uint32_t(*)[36])(sm + OFF_W2);
    uint32_t (*W3s)[36] = (uint32_t(*)[36])(sm + OFF_W3);
    uint32_t* bj_s = (uint32_t*)(sm + OFF_BJ);
    float* v_s  = (float*)(sm + OFF_V);
    float* b2_s = (float*)(sm + OFF_B2);
    float* b3_s = (float*)(sm + OFF_B3);
    float (*wpart)[32] = (float(*)[32])(sm + OFF_WP);

    int t = threadIdx.x;
    int lane = t & 31, wid = t >> 5;
    int j = blockIdx.x;

    // ---- stage h (swizzled bf16x2 words) via uint4 copies ----
#pragma unroll
    for (int ii = 0; ii < 16; ii++) {
        int idx = t + 128 * ii;                 // uint4 index, 2048 total
        uint4 g = ((const uint4*)g_hb)[idx];
        int r = idx >> 2, pg = (idx & 3) * 4;
        int pw = pg ^ ((r & 3) << 2);
        *(uint4*)(h_s + r * 16 + pw) = g;
    }
    // ---- stage W0 = [Wi (k0..31) | (wbi,wJ) word16 | zeros] ----
    for (int idx = t; idx < 64 * 28; idx += 128) {
        int r = idx / 28, w = idx % 28;
        uint32_t val = 0;
        if (w < 16) {
            val = cvt2(W1[r * 67 + 2 * w], W1[r * 67 + 2 * w + 1]);
        } else if (w == 16) {
            val = cvt2(W1[r * 67 + 65], W1[r * 67 + 64]);   // (wbi, wJ)
        }
        W0s[r][w] = val;
    }
    // ---- stage W2, W3 ----
    for (int idx = t; idx < 2048; idx += 128) {
        int r = idx >> 5, w = idx & 31;
        float2 p = *(const float2*)(W2 + r * 64 + 2 * w);
        W2s[r][w] = cvt2(p.x, p.y);
    }
    for (int idx = t; idx < 1024; idx += 128) {
        int r = idx >> 5, w = idx & 31;
        float2 p = *(const float2*)(W3 + r * 64 + 2 * w);
        W3s[r][w] = cvt2(p.x, p.y);
    }
    // ---- stage (b, J) pairs + v + biases ----
    for (int i = t; i < NN; i += 128)
        bj_s[i] = cvt2(b_in[i], g_Jt[(size_t)j * NN + i]);
    if (t < 64) {
        v_s[t]  = g_v[j * 64 + t];
        b2_s[t] = b2[t];
    }
    if (t < 32) b3_s[t] = b3[t];
    __syncthreads();

    const int q = lane & 3;
    const int q2 = q * 2;
    const int rsub = lane >> 2;
    const int brow = lane >> 2;
    const int bcol = lane & 3;

    float acc[4][2];
#pragma unroll
    for (int nt = 0; nt < 4; nt++) acc[nt][0] = acc[nt][1] = 0.f;

#pragma unroll 1
    for (int tb = wid; tb < 32; tb += 4) {
        int rA = tb * 16 + rsub;
        int rB = rA + 8;
        int xw = (rA & 3) << 2;                 // rB has same (r&3)

        // ---- A0 fragments: [h | b,J | 0] ----
        uint32_t a0[3][4];
#pragma unroll
        for (int kt = 0; kt < 2; kt++) {
            int p = kt * 8 + q;
            a0[kt][0] = h_s[rA * 16 + (p ^ xw)];
            a0[kt][1] = h_s[rB * 16 + (p ^ xw)];
            a0[kt][2] = h_s[rA * 16 + ((p + 4) ^ xw)];
            a0[kt][3] = h_s[rB * 16 + ((p + 4) ^ xw)];
        }
        a0[2][0] = (q == 0) ? bj_s[rA] : 0u;
        a0[2][1] = (q == 0) ? bj_s[rB] : 0u;
        a0[2][2] = 0u;
        a0[2][3] = 0u;

        // ---- MMA0: m1_pre(i-part) = [h|b|J] @ W0^T (16x64, K=48) ----
        float d0[8][4];
#pragma unroll
        for (int nt = 0; nt < 8; nt++) {
            d0[nt][0] = d0[nt][1] = d0[nt][2] = d0[nt][3] = 0.f;
#pragma unroll
            for (int kt = 0; kt < 3; kt++) {
                uint32_t b0 = W0s[nt * 8 + brow][kt * 8 + bcol];
                uint32_t b1 = W0s[nt * 8 + brow][kt * 8 + bcol + 4];
                mma16816(d0[nt], a0[kt], b0, b1);
            }
        }

        // ---- convert: relu(d0 + v_j) -> MMA1 A-fragments ----
        uint32_t a1[4][4];
#pragma unroll
        for (int kt = 0; kt < 4; kt++) {
            int n0i = 2 * kt, n1i = 2 * kt + 1;
            float p00 = v_s[n0i * 8 + q2], p01 = v_s[n0i * 8 + q2 + 1];
            float p10 = v_s[n1i * 8 + q2], p11 = v_s[n1i * 8 + q2 + 1];
            a1[kt][0] = cvt2(fmaxf(d0[n0i][0] + p00, 0.f),
                             fmaxf(d0[n0i][1] + p01, 0.f));
            a1[kt][1] = cvt2(fmaxf(d0[n0i][2] + p00, 0.f),
                             fmaxf(d0[n0i][3] + p01, 0.f));
            a1[kt][2] = cvt2(fmaxf(d0[n1i][0] + p10, 0.f),
                             fmaxf(d0[n1i][1] + p11, 0.f));
            a1[kt][3] = cvt2(fmaxf(d0[n1i][2] + p10, 0.f),
                             fmaxf(d0[n1i][3] + p11, 0.f));
        }

        // ---- MMA1: d1 = m1 @ W2^T (16x64, K=64) ----
        float d1[8][4];
#pragma unroll
        for (int nt = 0; nt < 8; nt++) {
            d1[nt][0] = d1[nt][1] = d1[nt][2] = d1[nt][3] = 0.f;
#pragma unroll
            for (int kt = 0; kt < 4; kt++) {
                uint32_t b0 = W2s[nt * 8 + brow][kt * 8 + bcol];
                uint32_t b1 = W2s[nt * 8 + brow][kt * 8 + bcol + 4];
                mma16816(d1[nt], a1[kt], b0, b1);
            }
        }

        // ---- convert: relu(d1 + b2) -> MMA2 A-fragments ----
        uint32_t a2f[4][4];
#pragma unroll
        for (int kt = 0; kt < 4; kt++) {
            int n0i = 2 * kt, n1i = 2 * kt + 1;
            float p00 = b2_s[n0i * 8 + q2], p01 = b2_s[n0i * 8 + q2 + 1];
            float p10 = b2_s[n1i * 8 + q2], p11 = b2_s[n1i * 8 + q2 + 1];
            a2f[kt][0] = cvt2(fmaxf(d1[n0i][0] + p00, 0.f),
                              fmaxf(d1[n0i][1] + p01, 0.f));
            a2f[kt][1] = cvt2(fmaxf(d1[n0i][2] + p00, 0.f),
                              fmaxf(d1[n0i][3] + p01, 0.f));
            a2f[kt][2] = cvt2(fmaxf(d1[n1i][0] + p10, 0.f),
                              fmaxf(d1[n1i][1] + p11, 0.f));
            a2f[kt][3] = cvt2(fmaxf(d1[n1i][2] + p10, 0.f),
                              fmaxf(d1[n1i][3] + p11, 0.f));
        }

        // ---- MMA2: d2 = m2 @ W3^T (16x32, K=64) + epi ----
#pragma unroll
        for (int nt = 0; nt < 4; nt++) {
            float d2[4] = {0.f, 0.f, 0.f, 0.f};
#pragma unroll
            for (int kt = 0; kt < 4; kt++) {
                uint32_t b0 = W3s[nt * 8 + brow][kt * 8 + bcol];
                uint32_t b1 = W3s[nt * 8 + brow][kt * 8 + bcol + 4];
                mma16816(d2, a2f[kt], b0, b1);
            }
            float bb0 = b3_s[nt * 8 + q2];
            float bb1 = b3_s[nt * 8 + q2 + 1];
            acc[nt][0] += fmaxf(d2[0] + bb0, 0.f) + fmaxf(d2[2] + bb0, 0.f);
            acc[nt][1] += fmaxf(d2[1] + bb1, 0.f) + fmaxf(d2[3] + bb1, 0.f);
        }
    }

    // ---- reduction ----
#pragma unroll
    for (int nt = 0; nt < 4; nt++)
#pragma unroll
        for (int c = 0; c < 2; c++) {
            float v = acc[nt][c];
            v += __shfl_xor_sync(0xFFFFFFFFu, v, 4);
            v += __shfl_xor_sync(0xFFFFFFFFu, v, 8);
            v += __shfl_xor_sync(0xFFFFFFFFu, v, 16);
            acc[nt][c] = v;
        }
    if (lane < 4) {
#pragma unroll
        for (int nt = 0; nt < 4; nt++) {
            wpart[wid][nt * 8 + lane * 2]     = acc[nt][0];
            wpart[wid][nt * 8 + lane * 2 + 1] = acc[nt][1];
        }
    }
    __syncthreads();
    if (t < 32)
        g_msum[j * 32 + t] = wpart[0][t] + wpart[1][t] + wpart[2][t] + wpart[3][t];
}

// ---------------- GRU (also emits bf16x2-packed h) ----------------
__global__ void __launch_bounds__(384) k_gru(const float* __restrict__ Wih,  // (96,64)
                                             const float* __restrict__ Whh,  // (96,32)
                                             const float* __restrict__ bih,
                                             const float* __restrict__ bhh) {
    __shared__ float Wih_s[96][65];
    __shared__ float Whh_s[96][33];
    __shared__ float x_s[4][64];
    __shared__ float gi_s[4][96], gh_s[4][96];
    int t = threadIdx.x;
    int n0 = blockIdx.x * 4;
    for (int idx = t; idx < 96 * 64; idx += 384) Wih_s[idx >> 6][idx & 63] = Wih[idx];
    for (int idx = t; idx < 96 * 32; idx += 384) Whh_s[idx >> 5][idx & 31] = Whh[idx];
    if (t < 256) {
        int nl = t >> 6, c = t & 63;
        x_s[nl][c] = (c < 32) ? g_h[(n0 + nl) * DD + c]
                              : g_msum[(n0 + nl) * DD + (c - 32)];
    }
    __syncthreads();
    int nl = t / 96, q = t % 96;
    float gi = bih[q], gh = bhh[q];
#pragma unroll
    for (int c = 0; c < 64; c++) gi = fmaf(x_s[nl][c], Wih_s[q][c], gi);
#pragma unroll
    for (int c = 0; c < 32; c++) gh = fmaf(x_s[nl][c], Whh_s[q][c], gh);
    gi_s[nl][q] = gi; gh_s[nl][q] = gh;
    __syncthreads();
    if (q < 32) {
        float r  = 1.f / (1.f + expf(-(gi_s[nl][q]      + gh_s[nl][q])));
        float z  = 1.f / (1.f + expf(-(gi_s[nl][32 + q] + gh_s[nl][32 + q])));
        float ng = tanhf(gi_s[nl][64 + q] + r * gh_s[nl][64 + q]);
        float hn = (1.f - z) * ng + z * x_s[nl][q];
        g_h[(n0 + nl) * DD + q] = hn;
        float hi = __shfl_down_sync(0xFFFFFFFFu, hn, 1);
        if ((q & 1) == 0)
            g_hb[(n0 + nl) * 16 + (q >> 1)] = cvt2(hn, hi);
    }
}

// ---------------- readout ----------------
__global__ void k_readout(const float* __restrict__ W1, const float* __restrict__ b1,
                          const float* __restrict__ W2, const float* __restrict__ b2,
                          const float* __restrict__ W3, const float* __restrict__ b3,
                          float* __restrict__ out) {
    int jn = blockIdx.x;
    int k = threadIdx.x;                 // 64 threads
    __shared__ float hs[DD], y1[64], y2[64];
    if (k < DD) hs[k] = g_h[jn * DD + k];
    __syncthreads();
    float a = b1[k];
    const float* w1 = W1 + k * DD;
#pragma unroll
    for (int c = 0; c < DD; c++) a = fmaf(hs[c], w1[c], a);
    y1[k] = fmaxf(a, 0.f);
    __syncthreads();
    float a2 = b2[k];
    const float* w2 = W2 + k * 64;
#pragma unroll
    for (int c = 0; c < 64; c++) a2 = fmaf(y1[c], w2[c], a2);
    y2[k] = fmaxf(a2, 0.f);
    __syncthreads();
    if (k < 2) {
        float a3 = b3[k];
        const float* w3 = W3 + k * 64;
#pragma unroll
        for (int c = 0; c < 64; c++) a3 = fmaf(y2[c], w3[c], a3);
        a3 = fmaxf(a3, 0.f);
        out[jn * 2 + k] = 1.f / (1.f + expf(-a3));
    }
}

extern "C" void kernel_launch(void* const* d_in, const int* in_sizes, int n_in,
                              void* d_out, int out_size) {
    const float* J   = (const float*)d_in[0];
    const float* b   = (const float*)d_in[1];
    const float* W1  = (const float*)d_in[2];
    const float* b1  = (const float*)d_in[3];
    const float* W2  = (const float*)d_in[4];
    const float* b2  = (const float*)d_in[5];
    const float* W3  = (const float*)d_in[6];
    const float* b3  = (const float*)d_in[7];
    const float* Wih = (const float*)d_in[8];
    const float* Whh = (const float*)d_in[9];
    const float* bih = (const float*)d_in[10];
    const float* bhh = (const float*)d_in[11];
    const float* rW1 = (const float*)d_in[12];
    const float* rb1 = (const float*)d_in[13];
    const float* rW2 = (const float*)d_in[14];
    const float* rb2 = (const float*)d_in[15];
    const float* rW3 = (const float*)d_in[16];
    const float* rb3 = (const float*)d_in[17];
    float* out = (float*)d_out;

    cudaFuncSetAttribute(k_msg, cudaFuncAttributeMaxDynamicSharedMemorySize,
                         MSG_SMEM);

    k_init<<<16, 1024>>>();
    k_tr<<<dim3(16, 16), dim3(32, 8)>>>(J);
    for (int s = 0; s < 5; s++) {
        k_v<<<64, 256>>>(b, W1, b1);
        k_msg<<<NN, 128, MSG_SMEM>>>(b, W1, W2, b2, W3, b3);
        k_gru<<<128, 384>>>(Wih, Whh, bih, bhh);
    }
    k_readout<<<NN, 64>>>(rW1, rb1, rW2, rb2, rW3, rb3, out);
}